// round 4
// baseline (speedup 1.0000x reference)
#include <cuda_runtime.h>
#include <math.h>

// Problem dims (fixed by the dataset):
//   inputs: [G=8, E=8, C=512, H=1024] f32
//   wi:     [E, H, F=4096] f32, bi: [E, F]
//   wo:     [E, F, H] f32,      bo: [E, H]
//   out:    [G, E, C, H] f32
// Per expert e: X_e (M=G*C=4096 x H) @ wi_e (H x F) -> gelu -> @ wo_e (F x H)

namespace {
constexpr int G = 8;
constexpr int E = 8;
constexpr int C = 512;
constexpr int H = 1024;
constexpr int F = 4096;
constexpr int M = G * C;   // 4096 rows per expert (g-major, strided by expert)

constexpr int BM = 128;
constexpr int BN = 128;
constexpr int BK = 16;
constexpr int PAD = 4;     // smem inner-dim pad (keeps 16B alignment: 132*4 % 16 == 0)
}

// Intermediate activations [E][M][F] = 537 MB. Static __device__ scratch is the
// sanctioned no-alloc workaround (see pitfalls.md).
constexpr size_t SCRATCH_ELEMS = (size_t)E * (size_t)M * (size_t)F;
__device__ float g_scratch[SCRATCH_ELEMS];

__device__ __forceinline__ float gelu_exact(float x) {
    // keras/jax exact gelu: 0.5*x*(1+erf(x/sqrt(2)))
    return 0.5f * x * (1.0f + erff(x * 0.70710678118654752440f));
}

template <bool FIRST>
__global__ __launch_bounds__(256)
void ffn_gemm(const float* __restrict__ X,
              const float* __restrict__ W,
              const float* __restrict__ bias,
              float* __restrict__ Out)
{
    constexpr int KD = FIRST ? H : F;   // reduction dim
    constexpr int ND = FIRST ? F : H;   // output cols

    __shared__ float As[BK][BM + PAD];  // transposed A tile: As[k][m]
    __shared__ float Bs[BK][BN + PAD];  // Bs[k][n]

    const int tid = threadIdx.x;
    const int e   = blockIdx.z;
    const int m0  = blockIdx.y * BM;
    const int n0  = blockIdx.x * BN;

    // ---- A loader: each thread loads 8 consecutive k's of one row ----
    const int arow = tid >> 1;          // 0..127
    const int acol = (tid & 1) * 8;     // 0 or 8
    const int mrow = m0 + arow;
    const float* aptr;
    if (FIRST) {
        // inputs[g][e][c][h], g = mrow/512, c = mrow%512
        aptr = X + ((size_t)((mrow >> 9) * E + e) * C + (mrow & 511)) * H + acol;
    } else {
        aptr = g_scratch + ((size_t)e * M + mrow) * (size_t)F + acol;
    }

    // ---- B loader: 16 k-rows x 128 n-cols, fully coalesced ----
    const int brow = tid >> 4;          // 0..15
    const int bcol = (tid & 15) * 8;    // 0..120
    const float* bptr = W + (size_t)e * KD * (size_t)ND
                          + (size_t)brow * ND + n0 + bcol;

    // ---- compute mapping: 16x16 threads, 8x8 outputs each ----
    const int ty = tid >> 4;
    const int tx = tid & 15;

    float acc[8][8];
    #pragma unroll
    for (int i = 0; i < 8; i++)
        #pragma unroll
        for (int j = 0; j < 8; j++)
            acc[i][j] = 0.0f;

    for (int k0 = 0; k0 < KD; k0 += BK) {
        const float4 a0 = *(const float4*)(aptr + k0);
        const float4 a1 = *(const float4*)(aptr + k0 + 4);
        const float4 b0 = *(const float4*)(bptr + (size_t)k0 * ND);
        const float4 b1 = *(const float4*)(bptr + (size_t)k0 * ND + 4);

        __syncthreads();   // previous tile fully consumed before overwrite

        As[acol + 0][arow] = a0.x;
        As[acol + 1][arow] = a0.y;
        As[acol + 2][arow] = a0.z;
        As[acol + 3][arow] = a0.w;
        As[acol + 4][arow] = a1.x;
        As[acol + 5][arow] = a1.y;
        As[acol + 6][arow] = a1.z;
        As[acol + 7][arow] = a1.w;
        *(float4*)&Bs[brow][bcol]     = b0;
        *(float4*)&Bs[brow][bcol + 4] = b1;

        __syncthreads();

        #pragma unroll
        for (int k = 0; k < BK; k++) {
            float a[8], b[8];
            *(float4*)&a[0] = *(const float4*)&As[k][ty * 8];
            *(float4*)&a[4] = *(const float4*)&As[k][ty * 8 + 4];
            *(float4*)&b[0] = *(const float4*)&Bs[k][tx * 8];
            *(float4*)&b[4] = *(const float4*)&Bs[k][tx * 8 + 4];
            #pragma unroll
            for (int i = 0; i < 8; i++)
                #pragma unroll
                for (int j = 0; j < 8; j++)
                    acc[i][j] = fmaf(a[i], b[j], acc[i][j]);
        }
    }

    // ---- epilogue: +bias, (gelu), store ----
    float bv[8];
    const float* bexp = bias + (size_t)e * ND + n0 + tx * 8;
    #pragma unroll
    for (int j = 0; j < 8; j++) bv[j] = bexp[j];

    #pragma unroll
    for (int i = 0; i < 8; i++) {
        const int m = m0 + ty * 8 + i;
        float* orow;
        if (FIRST) {
            orow = g_scratch + ((size_t)e * M + m) * (size_t)F + n0 + tx * 8;
        } else {
            orow = Out + ((size_t)((m >> 9) * E + e) * C + (m & 511)) * H + n0 + tx * 8;
        }
        float t[8];
        #pragma unroll
        for (int j = 0; j < 8; j++) {
            float x = acc[i][j] + bv[j];
            t[j] = FIRST ? gelu_exact(x) : x;
        }
        *(float4*)&orow[0] = make_float4(t[0], t[1], t[2], t[3]);
        *(float4*)&orow[4] = make_float4(t[4], t[5], t[6], t[7]);
    }
}

extern "C" void kernel_launch(void* const* d_in, const int* in_sizes, int n_in,
                              void* d_out, int out_size)
{
    const float* inputs = (const float*)d_in[0];
    const float* wi     = (const float*)d_in[1];
    const float* bi     = (const float*)d_in[2];
    const float* wo     = (const float*)d_in[3];
    const float* bo     = (const float*)d_in[4];
    float* out          = (float*)d_out;

    dim3 blk(256);
    dim3 g1(F / BN, M / BM, E);   // (32, 32, 8)
    dim3 g2(H / BN, M / BM, E);   // ( 8, 32, 8)

    ffn_gemm<true ><<<g1, blk>>>(inputs, wi, bi, nullptr);
    ffn_gemm<false><<<g2, blk>>>(nullptr, wo, bo, out);
}

// round 7
// speedup vs baseline: 4.2774x; 4.2774x over previous
#include <cuda_runtime.h>
#include <cuda_bf16.h>
#include <math.h>
#include <stdint.h>

// FeedForwardExperts, per expert e (E=8):
//   X_e [M=4096, H=1024] @ Wi_e [H, F=4096] -> +bi, exact gelu -> @ Wo_e [F, H] -> +bo
// HMMA (mma.sync bf16) with split-precision operands: x = hi + lo (bf16 each),
// 3 MMAs per K16: Ahi*Bhi + Ahi*Blo + Alo*Bhi, fp32 accumulate.
// (tcgen05 is unavailable: harness PTX target is compute_103, not 103a.)
// R7: identical compute path to R6 submission — R6 failed at the infra level
// (container death, no compile/run output), so this re-runs the experiment.

namespace {
constexpr int G = 8, E = 8, C = 512, H = 1024, F = 4096;
constexpr int M = G * C;                 // 4096 rows per expert
constexpr int BM = 128, BN = 128, BK = 32;
constexpr int STAGES = 3;
constexpr int LDA_S = 80;                // A smem row stride bytes (64 data + 16 pad)
constexpr int LDB_S = 272;               // B smem row stride bytes (256 data + 16 pad)
constexpr int A_PLANE = BM * LDA_S;      // 10240
constexpr int B_PLANE = BK * LDB_S;      // 8704
constexpr int STAGEB = 2 * A_PLANE + 2 * B_PLANE;  // 37888
constexpr int SMEM_BYTES = STAGES * STAGEB + 256;  // ~114 KB
}

// ---- device scratch (statics; no allocs allowed) ----
__device__ __nv_bfloat16 g_x_hi [(size_t)G * E * C * H];
__device__ __nv_bfloat16 g_x_lo [(size_t)G * E * C * H];
__device__ __nv_bfloat16 g_wi_hi[(size_t)E * H * F];
__device__ __nv_bfloat16 g_wi_lo[(size_t)E * H * F];
__device__ __nv_bfloat16 g_wo_hi[(size_t)E * F * H];
__device__ __nv_bfloat16 g_wo_lo[(size_t)E * F * H];
__device__ __nv_bfloat16 g_act_hi[(size_t)E * M * F];
__device__ __nv_bfloat16 g_act_lo[(size_t)E * M * F];

// ---------------- helpers ----------------
__device__ __forceinline__ uint32_t smem_u32(const void* p) {
    uint32_t a;
    asm("{ .reg .u64 t; cvta.to.shared.u64 t, %1; cvt.u32.u64 %0, t; }" : "=r"(a) : "l"(p));
    return a;
}
__device__ __forceinline__ void cp_async16(uint32_t dst, const void* src) {
    asm volatile("cp.async.cg.shared.global [%0], [%1], 16;" :: "r"(dst), "l"(src));
}
__device__ __forceinline__ void cp_commit() {
    asm volatile("cp.async.commit_group;");
}
template <int N>
__device__ __forceinline__ void cp_wait() {
    asm volatile("cp.async.wait_group %0;" :: "n"(N));
}
__device__ __forceinline__ void ldsm_x4(uint32_t* r, uint32_t addr) {
    asm volatile("ldmatrix.sync.aligned.m8n8.x4.shared.b16 {%0,%1,%2,%3}, [%4];"
                 : "=r"(r[0]), "=r"(r[1]), "=r"(r[2]), "=r"(r[3]) : "r"(addr));
}
__device__ __forceinline__ void ldsm_x4_t(uint32_t* r, uint32_t addr) {
    asm volatile("ldmatrix.sync.aligned.m8n8.x4.trans.shared.b16 {%0,%1,%2,%3}, [%4];"
                 : "=r"(r[0]), "=r"(r[1]), "=r"(r[2]), "=r"(r[3]) : "r"(addr));
}
__device__ __forceinline__ void mma_bf16(float* d, const uint32_t* a, const uint32_t* b) {
    asm volatile(
        "mma.sync.aligned.m16n8k16.row.col.f32.bf16.bf16.f32 "
        "{%0,%1,%2,%3}, {%4,%5,%6,%7}, {%8,%9}, {%0,%1,%2,%3};"
        : "+f"(d[0]), "+f"(d[1]), "+f"(d[2]), "+f"(d[3])
        : "r"(a[0]), "r"(a[1]), "r"(a[2]), "r"(a[3]), "r"(b[0]), "r"(b[1]));
}
__device__ __forceinline__ uint32_t bfpack(__nv_bfloat16 a, __nv_bfloat16 b) {
    __nv_bfloat162 t; t.x = a; t.y = b;
    return *reinterpret_cast<uint32_t*>(&t);
}
__device__ __forceinline__ float gelu_exact(float x) {
    return 0.5f * x * (1.0f + erff(x * 0.70710678118654752440f));
}

// ---------------- elementwise hi/lo split (prep) ----------------
// SEL: 0 = inputs -> g_x, 1 = wi -> g_wi, 2 = wo -> g_wo
template <int SEL>
__global__ __launch_bounds__(256)
void split_kernel(const float* __restrict__ src)
{
    __nv_bfloat16* __restrict__ hi = (SEL == 0) ? g_x_hi : (SEL == 1) ? g_wi_hi : g_wo_hi;
    __nv_bfloat16* __restrict__ lo = (SEL == 0) ? g_x_lo : (SEL == 1) ? g_wi_lo : g_wo_lo;
    const size_t i = (size_t)blockIdx.x * 256 + threadIdx.x;   // in float4 units
    float4 v = reinterpret_cast<const float4*>(src)[i];
    __nv_bfloat16 hx = __float2bfloat16_rn(v.x);
    __nv_bfloat16 hy = __float2bfloat16_rn(v.y);
    __nv_bfloat16 hz = __float2bfloat16_rn(v.z);
    __nv_bfloat16 hw = __float2bfloat16_rn(v.w);
    uint2 ph = make_uint2(bfpack(hx, hy), bfpack(hz, hw));
    uint2 pl = make_uint2(
        bfpack(__float2bfloat16_rn(v.x - __bfloat162float(hx)),
               __float2bfloat16_rn(v.y - __bfloat162float(hy))),
        bfpack(__float2bfloat16_rn(v.z - __bfloat162float(hz)),
               __float2bfloat16_rn(v.w - __bfloat162float(hw))));
    reinterpret_cast<uint2*>(hi)[i] = ph;
    reinterpret_cast<uint2*>(lo)[i] = pl;
}

// ---------------- HMMA GEMM ----------------
template <bool FIRST>
__global__ __launch_bounds__(256, 1)
void ffn_hmma(const float* __restrict__ bias, float* __restrict__ Out)
{
    constexpr int KD = FIRST ? H : F;          // reduction dim
    constexpr int NC = KD / BK;                // k-chunks
    constexpr int ldA = FIRST ? H : F;         // elems
    constexpr int ldB = FIRST ? F : H;

    extern __shared__ char dsm[];
    const uint32_t sbase = smem_u32(dsm);
    const uint32_t data0 = (sbase + 255) & ~255u;

    const int tid = threadIdx.x, wid = tid >> 5, lane = tid & 31;
    const int e  = blockIdx.z;
    const int m0 = blockIdx.y * BM;
    const int n0 = blockIdx.x * BN;
    const int wm = wid & 3;        // 4 m-groups of 32 rows
    const int wn = wid >> 2;       // 2 n-groups of 64 cols

    // global bf16 plane bases
    const __nv_bfloat16 *Ah, *Al, *Bh, *Bl;
    if (FIRST) {
        const int g = m0 >> 9, cb = m0 & 511;
        const size_t ab = ((size_t)(g * E + e) * C + cb) * H;
        Ah = g_x_hi + ab;  Al = g_x_lo + ab;
        const size_t bb = (size_t)e * H * F + n0;
        Bh = g_wi_hi + bb; Bl = g_wi_lo + bb;
    } else {
        const size_t ab = ((size_t)e * M + m0) * (size_t)F;
        Ah = g_act_hi + ab; Al = g_act_lo + ab;
        const size_t bb = (size_t)e * F * H + n0;
        Bh = g_wo_hi + bb;  Bl = g_wo_lo + bb;
    }

    auto load_chunk = [&](int c, int slot) {
        const uint32_t st   = data0 + slot * STAGEB;
        const uint32_t sAh  = st;
        const uint32_t sAl  = st + A_PLANE;
        const uint32_t sBh  = st + 2 * A_PLANE;
        const uint32_t sBl  = st + 2 * A_PLANE + B_PLANE;
        const int k0 = c * BK;
        #pragma unroll
        for (int it = 0; it < 2; ++it) {           // A: 512 16B chunks per plane
            const int idx = it * 256 + tid;
            const int row = idx >> 2, c4 = idx & 3;
            const size_t go = (size_t)row * ldA + k0 + c4 * 8;
            const uint32_t so = row * LDA_S + c4 * 16;
            cp_async16(sAh + so, Ah + go);
            cp_async16(sAl + so, Al + go);
        }
        #pragma unroll
        for (int it = 0; it < 2; ++it) {           // B: 512 16B chunks per plane
            const int idx = it * 256 + tid;
            const int row = idx >> 4, c4 = idx & 15;
            const size_t go = (size_t)(k0 + row) * ldB + c4 * 8;
            const uint32_t so = row * LDB_S + c4 * 16;
            cp_async16(sBh + so, Bh + go);
            cp_async16(sBl + so, Bl + go);
        }
    };

    float acc[2][8][4];
    #pragma unroll
    for (int i = 0; i < 2; i++)
        #pragma unroll
        for (int j = 0; j < 8; j++)
            #pragma unroll
            for (int q = 0; q < 4; q++) acc[i][j][q] = 0.0f;

    // prologue: prefetch STAGES-1 chunks
    #pragma unroll
    for (int s = 0; s < STAGES - 1; ++s) { load_chunk(s, s); cp_commit(); }

    for (int c = 0; c < NC; ++c) {
        cp_wait<STAGES - 2>();
        __syncthreads();

        const int slot = c % STAGES;
        const uint32_t st  = data0 + slot * STAGEB;
        // per-lane base addresses
        const uint32_t aBase = st + (wm * 32 + (lane & 15)) * LDA_S + (lane >> 4) * 16;
        const uint32_t bBase = st + 2 * A_PLANE + (lane & 15) * LDB_S
                             + wn * 128 + (lane >> 4) * 16;   // wn*64 cols * 2B

        #pragma unroll
        for (int k16 = 0; k16 < 2; ++k16) {
            uint32_t ah[2][4], al[2][4], bh[4][4], bl[4][4];
            #pragma unroll
            for (int mi = 0; mi < 2; ++mi) {
                const uint32_t a = aBase + mi * 16 * LDA_S + k16 * 32;
                ldsm_x4(ah[mi], a);
                ldsm_x4(al[mi], a + A_PLANE);
            }
            #pragma unroll
            for (int ni = 0; ni < 4; ++ni) {
                const uint32_t b = bBase + k16 * 16 * LDB_S + ni * 32;
                ldsm_x4_t(bh[ni], b);
                ldsm_x4_t(bl[ni], b + B_PLANE);
            }
            #pragma unroll
            for (int mi = 0; mi < 2; ++mi)
                #pragma unroll
                for (int n8 = 0; n8 < 8; ++n8) {
                    const uint32_t* Bhf = &bh[n8 >> 1][(n8 & 1) * 2];
                    const uint32_t* Blf = &bl[n8 >> 1][(n8 & 1) * 2];
                    mma_bf16(acc[mi][n8], ah[mi], Bhf);   // hi*hi
                    mma_bf16(acc[mi][n8], ah[mi], Blf);   // hi*lo
                    mma_bf16(acc[mi][n8], al[mi], Bhf);   // lo*hi
                }
        }

        if (c + STAGES - 1 < NC) load_chunk(c + STAGES - 1, (c + STAGES - 1) % STAGES);
        cp_commit();   // commit (possibly empty) to keep group accounting uniform
    }

    // ---------------- epilogue ----------------
    const int r0 = (lane >> 2);            // 0..7
    const int cl = (lane & 3) * 2;         // 0,2,4,6
    if (FIRST) {
        const float* bv = bias + (size_t)e * F;
        #pragma unroll
        for (int mi = 0; mi < 2; ++mi) {
            const int mbase = m0 + wm * 32 + mi * 16;
            #pragma unroll
            for (int n8 = 0; n8 < 8; ++n8) {
                const int col = n0 + wn * 64 + n8 * 8 + cl;
                const float b0 = bv[col], b1 = bv[col + 1];
                #pragma unroll
                for (int half = 0; half < 2; ++half) {
                    const int m = mbase + r0 + half * 8;
                    const float x0 = acc[mi][n8][half * 2]     + b0;
                    const float x1 = acc[mi][n8][half * 2 + 1] + b1;
                    const float g0 = gelu_exact(x0), g1 = gelu_exact(x1);
                    const __nv_bfloat16 h0 = __float2bfloat16_rn(g0);
                    const __nv_bfloat16 h1 = __float2bfloat16_rn(g1);
                    const size_t off = ((size_t)e * M + m) * (size_t)F + col;
                    *(uint32_t*)&g_act_hi[off] = bfpack(h0, h1);
                    *(uint32_t*)&g_act_lo[off] =
                        bfpack(__float2bfloat16_rn(g0 - __bfloat162float(h0)),
                               __float2bfloat16_rn(g1 - __bfloat162float(h1)));
                }
            }
        }
    } else {
        const float* bv = bias + (size_t)e * H;
        #pragma unroll
        for (int mi = 0; mi < 2; ++mi) {
            const int mbase = m0 + wm * 32 + mi * 16;
            #pragma unroll
            for (int n8 = 0; n8 < 8; ++n8) {
                const int col = n0 + wn * 64 + n8 * 8 + cl;
                const float b0 = bv[col], b1 = bv[col + 1];
                #pragma unroll
                for (int half = 0; half < 2; ++half) {
                    const int m = mbase + r0 + half * 8;
                    const int g = m >> 9, cc = m & 511;
                    float2 o;
                    o.x = acc[mi][n8][half * 2]     + b0;
                    o.y = acc[mi][n8][half * 2 + 1] + b1;
                    *(float2*)&Out[((size_t)(g * E + e) * C + cc) * (size_t)H + col] = o;
                }
            }
        }
    }
}

extern "C" void kernel_launch(void* const* d_in, const int* in_sizes, int n_in,
                              void* d_out, int out_size)
{
    const float* inputs = (const float*)d_in[0];
    const float* wi     = (const float*)d_in[1];
    const float* bi     = (const float*)d_in[2];
    const float* wo     = (const float*)d_in[3];
    const float* bo     = (const float*)d_in[4];
    float* out          = (float*)d_out;

    cudaFuncSetAttribute(ffn_hmma<true>,  cudaFuncAttributeMaxDynamicSharedMemorySize, SMEM_BYTES);
    cudaFuncSetAttribute(ffn_hmma<false>, cudaFuncAttributeMaxDynamicSharedMemorySize, SMEM_BYTES);

    // prep: split fp32 -> bf16 hi/lo planes
    split_kernel<0><<<(G * E * C * (H / 4)) / 256, 256>>>(inputs);  // 33.5M elems
    split_kernel<1><<<(E * H * (F / 4)) / 256, 256>>>(wi);
    split_kernel<2><<<(E * F * (H / 4)) / 256, 256>>>(wo);

    ffn_hmma<true ><<<dim3(F / BN, M / BM, E), 256, SMEM_BYTES>>>(bi, nullptr);
    ffn_hmma<false><<<dim3(H / BN, M / BM, E), 256, SMEM_BYTES>>>(bo, out);
}